// round 3
// baseline (speedup 1.0000x reference)
#include <cuda_runtime.h>
#include <math.h>

#define BB 256
#define NN 4096
#define KK 64
#define CS_STRIDE 68   // 64 + 4 pad, keeps 16B alignment (68*4 = 272 = 17*16)
#define AS_STRIDE 65
#define NCHUNKS 16     // N / 256

// ---------------- scratch (static device globals; no allocation) -------------
__device__ float g_Ct[NN * KK];              // C'[n][k] = C[k][n] * rsqrt(psi[n])  (1 MB)
__device__ float g_Gpart[NCHUNKS * KK * KK]; // partial Gram matrices
__device__ float g_G[KK * KK];               // I + C' C'^T
__device__ float g_dp[BB * NN];              // masked residual / sqrt(psi)        (4 MB)
__device__ int   g_idx[BB * NN];             // compacted unmasked indices per row (4 MB)
__device__ int   g_cnt[BB];
__device__ float g_scal[BB * 8];             // per-row scalar reductions
__device__ float g_Upart[NCHUNKS * BB * KK]; // partial u vectors

// ---------------- kernel 1: build scaled transposed C ------------------------
__global__ void k_prep(const float* __restrict__ C, const float* __restrict__ psi) {
    int idx = blockIdx.x * 256 + threadIdx.x;   // idx = k*NN + n, n fastest -> coalesced read
    int n = idx & (NN - 1);
    int k = idx >> 12;
    g_Ct[n * KK + k] = C[idx] * rsqrtf(psi[n]);
}

// ---------------- kernel 2: partial Gram (SYRK over 256-column chunks) -------
__global__ void k_gpart() {
    __shared__ float Cs[64 * CS_STRIDE];
    int tid = threadIdx.x;
    int ty = tid >> 4, tx = tid & 15;
    int r = tid >> 2, q = tid & 3;
    float acc[4][4] = {};
    for (int sub = 0; sub < 4; sub++) {
        int n0 = blockIdx.x * 256 + sub * 64;
        const float4* src = (const float4*)(g_Ct + (n0 + r) * KK + q * 16);
#pragma unroll
        for (int i = 0; i < 4; i++)
            *(float4*)&Cs[r * CS_STRIDE + q * 16 + i * 4] = src[i];
        __syncthreads();
#pragma unroll 16
        for (int s = 0; s < 64; s++) {
            float4 a4 = *(const float4*)&Cs[s * CS_STRIDE + ty * 4];
            float4 b4 = *(const float4*)&Cs[s * CS_STRIDE + tx * 4];
            float av[4] = {a4.x, a4.y, a4.z, a4.w};
            float bv[4] = {b4.x, b4.y, b4.z, b4.w};
#pragma unroll
            for (int i = 0; i < 4; i++)
#pragma unroll
                for (int j = 0; j < 4; j++) acc[i][j] = fmaf(av[i], bv[j], acc[i][j]);
        }
        __syncthreads();
    }
    float* out = g_Gpart + blockIdx.x * KK * KK;
#pragma unroll
    for (int i = 0; i < 4; i++)
#pragma unroll
        for (int j = 0; j < 4; j++)
            out[(ty * 4 + i) * KK + tx * 4 + j] = acc[i][j];
}

// ---------------- kernel 3: reduce Gram partials, add identity ---------------
__global__ void k_greduce() {
    int i = blockIdx.x * 256 + threadIdx.x;   // grid = 16
    float s = 0.f;
#pragma unroll
    for (int p = 0; p < NCHUNKS; p++) s += g_Gpart[p * KK * KK + i];
    if ((i >> 6) == (i & 63)) s += 1.0f;
    g_G[i] = s;
}

// ---------------- kernel 4: elementwise pass + deterministic compaction ------
__global__ void k_ew(const float* __restrict__ targets, const float* __restrict__ rho,
                     const float* __restrict__ qs, const float* __restrict__ means,
                     const float* __restrict__ psi) {
    __shared__ int warpcnt[8];
    __shared__ float wred[5 * 8];
    int b = blockIdx.x, tid = threadIdx.x;
    int lane = tid & 31, w = tid >> 5;
    float rho_s = rho[0];
    float logrho = logf(rho_s);
    const float* tg = targets + b * NN;
    const float* qp = qs + b * NN;
    const float* mp = means + b * NN;

    float uni = 0.f, extra = 0.f, wd2 = 0.f, slogpsi = 0.f, nb = 0.f;
    int running = 0;

    for (int it = 0; it < 16; it++) {
        int n = it * 256 + tid;
        float t = tg[n], qv = qp[n], mu = mp[n], ps = psi[n];
        bool masked = (t >= rho_s);
        if (masked) {
            float lt = logf(t);
            float dpv = (lt - mu) * rsqrtf(ps);
            wd2 += dpv * dpv;
            slogpsi += logf(ps);
            nb += 1.0f;
            extra += logf(qv) - lt;
            g_dp[b * NN + n] = dpv;
        } else {
            uni += log1pf(-qv) - logrho;
            g_dp[b * NN + n] = 0.0f;
        }
        // deterministic compaction of UNMASKED indices (ascending n)
        unsigned bal = __ballot_sync(0xffffffffu, !masked);
        if (lane == 0) warpcnt[w] = __popc(bal);
        __syncthreads();
        int off = running;
        for (int ww = 0; ww < w; ww++) off += warpcnt[ww];
        if (!masked) {
            int myoff = off + __popc(bal & ((1u << lane) - 1u));
            g_idx[b * NN + myoff] = n;
        }
        int tot = 0;
#pragma unroll
        for (int ww = 0; ww < 8; ww++) tot += warpcnt[ww];
        running += tot;
        __syncthreads();
    }

    float vals[5] = {uni, extra, wd2, slogpsi, nb};
#pragma unroll
    for (int q5 = 0; q5 < 5; q5++) {
        float v = vals[q5];
#pragma unroll
        for (int off2 = 16; off2 > 0; off2 >>= 1) v += __shfl_xor_sync(0xffffffffu, v, off2);
        if (lane == 0) wred[q5 * 8 + w] = v;
    }
    __syncthreads();
    if (tid == 0) {
#pragma unroll
        for (int q5 = 0; q5 < 5; q5++) {
            float s = 0.f;
#pragma unroll
            for (int ww = 0; ww < 8; ww++) s += wred[q5 * 8 + ww];
            g_scal[b * 8 + q5] = s;
        }
        g_cnt[b] = running;
    }
}

// ---------------- kernel 5: partial U = dp @ Ct (batched, Ct reused) ---------
__global__ void k_upart() {
    __shared__ float DPt[64 * CS_STRIDE];
    __shared__ float Cts[64 * CS_STRIDE];
    int tid = threadIdx.x;
    int ty = tid >> 4, tx = tid & 15;
    int r = tid >> 2, q = tid & 3;
    int btile = blockIdx.x * 64;   // gridDim.x = 4
    int nch = blockIdx.y;          // gridDim.y = 16
    float acc[4][4] = {};
    for (int sub = 0; sub < 4; sub++) {
        int n0 = nch * 256 + sub * 64;
        const float4* cs = (const float4*)(g_Ct + (n0 + r) * KK + q * 16);
        const float4* ds = (const float4*)(g_dp + (btile + r) * NN + n0 + q * 16);
#pragma unroll
        for (int i = 0; i < 4; i++) {
            *(float4*)&Cts[r * CS_STRIDE + q * 16 + i * 4] = cs[i];
            float4 dv = ds[i];
            DPt[(q * 16 + i * 4 + 0) * CS_STRIDE + r] = dv.x;
            DPt[(q * 16 + i * 4 + 1) * CS_STRIDE + r] = dv.y;
            DPt[(q * 16 + i * 4 + 2) * CS_STRIDE + r] = dv.z;
            DPt[(q * 16 + i * 4 + 3) * CS_STRIDE + r] = dv.w;
        }
        __syncthreads();
#pragma unroll 16
        for (int s = 0; s < 64; s++) {
            float4 a4 = *(const float4*)&DPt[s * CS_STRIDE + ty * 4];
            float4 b4 = *(const float4*)&Cts[s * CS_STRIDE + tx * 4];
            float av[4] = {a4.x, a4.y, a4.z, a4.w};
            float bv[4] = {b4.x, b4.y, b4.z, b4.w};
#pragma unroll
            for (int i = 0; i < 4; i++)
#pragma unroll
                for (int j = 0; j < 4; j++) acc[i][j] = fmaf(av[i], bv[j], acc[i][j]);
        }
        __syncthreads();
    }
#pragma unroll
    for (int i = 0; i < 4; i++)
#pragma unroll
        for (int j = 0; j < 4; j++)
            g_Upart[nch * BB * KK + (btile + ty * 4 + i) * KK + (tx * 4 + j)] = acc[i][j];
}

// ---------------- kernel 6: per-b correction GEMM + Cholesky + solve ---------
__global__ void __launch_bounds__(256, 2) k_main(float* __restrict__ out) {
    __shared__ float Cs[64 * CS_STRIDE];
    __shared__ float As[64 * AS_STRIDE];
    __shared__ float u_s[64], col_s[64], diag_s[64], z_s[64];
    int b = blockIdx.x, tid = threadIdx.x;
    int ty = tid >> 4, tx = tid & 15;
    int r = tid >> 2, q = tid & 3;

    if (tid < 64) {
        float s = 0.f;
#pragma unroll
        for (int p = 0; p < NCHUNKS; p++) s += g_Upart[p * BB * KK + b * KK + tid];
        u_s[tid] = s;
    }

    float acc[4][4];
#pragma unroll
    for (int i = 0; i < 4; i++)
#pragma unroll
        for (int j = 0; j < 4; j++)
            acc[i][j] = g_G[(ty * 4 + i) * KK + tx * 4 + j];

    int cnt = g_cnt[b];
    int tiles = (cnt + 63) >> 6;
    const int* idxp = g_idx + b * NN;

    for (int t = 0; t < tiles; t++) {
        int p = t * 64 + r;
        if (p < cnt) {
            int n = idxp[p];
            const float4* src = (const float4*)(g_Ct + n * KK + q * 16);
#pragma unroll
            for (int i = 0; i < 4; i++)
                *(float4*)&Cs[r * CS_STRIDE + q * 16 + i * 4] = src[i];
        } else {
            float4 z4 = {0.f, 0.f, 0.f, 0.f};
#pragma unroll
            for (int i = 0; i < 4; i++)
                *(float4*)&Cs[r * CS_STRIDE + q * 16 + i * 4] = z4;
        }
        __syncthreads();
#pragma unroll 16
        for (int s = 0; s < 64; s++) {
            float4 a4 = *(const float4*)&Cs[s * CS_STRIDE + ty * 4];
            float4 b4 = *(const float4*)&Cs[s * CS_STRIDE + tx * 4];
            float av[4] = {a4.x, a4.y, a4.z, a4.w};
            float bv[4] = {b4.x, b4.y, b4.z, b4.w};
#pragma unroll
            for (int i = 0; i < 4; i++)
#pragma unroll
                for (int j = 0; j < 4; j++) acc[i][j] = fmaf(-av[i], bv[j], acc[i][j]);
        }
        __syncthreads();
    }

#pragma unroll
    for (int i = 0; i < 4; i++)
#pragma unroll
        for (int j = 0; j < 4; j++)
            As[(ty * 4 + i) * AS_STRIDE + tx * 4 + j] = acc[i][j];
    __syncthreads();

    // ---- Cholesky (lower), block-parallel ----
    float logdet = 0.f;
    for (int j = 0; j < 64; j++) {
        float d = sqrtf(As[j * AS_STRIDE + j]);   // all threads, redundant (post-sync read)
        logdet += logf(d);
        float inv = 1.0f / d;
        if (tid == 0) diag_s[j] = d;
        int i2 = j + 1 + tid;
        if (i2 < 64) {
            float v = As[i2 * AS_STRIDE + j] * inv;
            As[i2 * AS_STRIDE + j] = v;
            col_s[i2] = v;
        }
        __syncthreads();
        int sz = 63 - j;
        for (int p2 = tid; p2 < sz * sz; p2 += 256) {
            int rr = j + 1 + p2 / sz;
            int cc = j + 1 + p2 % sz;
            As[rr * AS_STRIDE + cc] -= col_s[rr] * col_s[cc];
        }
        __syncthreads();
    }

    // ---- forward solve L z = u;  u^T A^-1 u = ||z||^2 ----
    if (tid < 64) z_s[tid] = u_s[tid];
    __syncthreads();
    float zz = 0.f;
    for (int j = 0; j < 64; j++) {
        float zj = z_s[j] / diag_s[j];
        zz += zj * zj;
        int rr = j + 1 + tid;
        if (rr < 64) z_s[rr] -= As[rr * AS_STRIDE + j] * zj;
        __syncthreads();
    }

    if (tid == 0) {
        float uni   = g_scal[b * 8 + 0];
        float extra = g_scal[b * 8 + 1];
        float wd2   = g_scal[b * 8 + 2];
        float slp   = g_scal[b * 8 + 3];
        float nb    = g_scal[b * 8 + 4];
        float logdetA = 2.0f * logdet;
        const float LOG2PI = 1.8378770664093453f;
        float gauss = -0.5f * (nb * LOG2PI + (slp + logdetA) + (wd2 - zz));
        out[b] = uni + gauss + extra;
    }
}

// ---------------- launch ------------------------------------------------------
extern "C" void kernel_launch(void* const* d_in, const int* in_sizes, int n_in,
                              void* d_out, int out_size) {
    const float* targets = (const float*)d_in[0];
    const float* rho     = (const float*)d_in[1];
    const float* qs      = (const float*)d_in[2];
    const float* means   = (const float*)d_in[3];
    const float* C       = (const float*)d_in[4];
    const float* psi     = (const float*)d_in[5];
    float* out = (float*)d_out;

    k_prep<<<(NN * KK) / 256, 256>>>(C, psi);
    k_gpart<<<NCHUNKS, 256>>>();
    k_greduce<<<(KK * KK) / 256, 256>>>();
    k_ew<<<BB, 256>>>(targets, rho, qs, means, psi);
    k_upart<<<dim3(BB / 64, NCHUNKS), 256>>>();
    k_main<<<BB, 256>>>(out);
}

// round 5
// speedup vs baseline: 1.1252x; 1.1252x over previous
#include <cuda_runtime.h>
#include <math.h>

#define BB 256
#define NN 4096
#define KK 64
#define CS_STRIDE 68   // 64 + 4 pad; 68*4 = 272 = 17*16 bytes, keeps 16B alignment
#define AS_STRIDE 65
#define NCHUNKS 16     // N / 256

// ---------------- packed f32x2 helpers (Blackwell full-rate fp32) ------------
__device__ __forceinline__ void fma2(unsigned long long& acc, unsigned long long a,
                                     unsigned long long b) {
    asm("fma.rn.f32x2 %0, %1, %2, %0;" : "+l"(acc) : "l"(a), "l"(b));
}
__device__ __forceinline__ unsigned long long pack2(float lo, float hi) {
    unsigned long long r;
    asm("mov.b64 %0, {%1, %2};" : "=l"(r) : "f"(lo), "f"(hi));
    return r;
}
__device__ __forceinline__ void unpack2(unsigned long long v, float& lo, float& hi) {
    asm("mov.b64 {%0, %1}, %2;" : "=f"(lo), "=f"(hi) : "l"(v));
}

// ---------------- scratch (static device globals; no allocation) -------------
__device__ float g_Ct[NN * KK];              // C'[n][k] = C[k][n] * rsqrt(psi[n])  (1 MB)
__device__ float g_Gpart[NCHUNKS * KK * KK]; // partial Gram matrices
__device__ float g_G[KK * KK];               // I + C' C'^T
__device__ float g_dp[BB * NN];              // masked residual / sqrt(psi)        (4 MB)
__device__ int   g_idx[BB * NN];             // compacted unmasked indices per row (4 MB)
__device__ int   g_cnt[BB];
__device__ float g_scal[BB * 8];             // per-row scalar reductions
__device__ float g_Upart[NCHUNKS * BB * KK]; // partial u vectors

// ---------------- kernel 1: build scaled transposed C ------------------------
__global__ void k_prep(const float* __restrict__ C, const float* __restrict__ psi) {
    int idx = blockIdx.x * 256 + threadIdx.x;   // idx = k*NN + n, n fastest -> coalesced read
    int n = idx & (NN - 1);
    int k = idx >> 12;
    g_Ct[n * KK + k] = C[idx] * rsqrtf(psi[n]);
}

// ---------------- kernel 2: partial Gram (SYRK over 256-column chunks) -------
__global__ void k_gpart() {
    __shared__ float Cs[64 * CS_STRIDE];
    int tid = threadIdx.x;
    int ty = tid >> 4, tx = tid & 15;
    int r = tid >> 2, q = tid & 3;
    unsigned long long acc2[2][4];
#pragma unroll
    for (int ip = 0; ip < 2; ip++)
#pragma unroll
        for (int j = 0; j < 4; j++) acc2[ip][j] = 0ull;

    for (int sub = 0; sub < 4; sub++) {
        int n0 = blockIdx.x * 256 + sub * 64;
        const float4* src = (const float4*)(g_Ct + (n0 + r) * KK + q * 16);
#pragma unroll
        for (int i = 0; i < 4; i++)
            *(float4*)&Cs[r * CS_STRIDE + q * 16 + i * 4] = src[i];
        __syncthreads();
#pragma unroll 16
        for (int s = 0; s < 64; s++) {
            const unsigned long long* ap =
                (const unsigned long long*)&Cs[s * CS_STRIDE + ty * 4];
            unsigned long long a01 = ap[0], a23 = ap[1];
            float4 b4 = *(const float4*)&Cs[s * CS_STRIDE + tx * 4];
            unsigned long long bd0 = pack2(b4.x, b4.x), bd1 = pack2(b4.y, b4.y);
            unsigned long long bd2 = pack2(b4.z, b4.z), bd3 = pack2(b4.w, b4.w);
            fma2(acc2[0][0], a01, bd0); fma2(acc2[0][1], a01, bd1);
            fma2(acc2[0][2], a01, bd2); fma2(acc2[0][3], a01, bd3);
            fma2(acc2[1][0], a23, bd0); fma2(acc2[1][1], a23, bd1);
            fma2(acc2[1][2], a23, bd2); fma2(acc2[1][3], a23, bd3);
        }
        __syncthreads();
    }
    float* out = g_Gpart + blockIdx.x * KK * KK;
#pragma unroll
    for (int ip = 0; ip < 2; ip++)
#pragma unroll
        for (int j = 0; j < 4; j++) {
            float lo, hi;
            unpack2(acc2[ip][j], lo, hi);
            out[(ty * 4 + 2 * ip + 0) * KK + tx * 4 + j] = lo;
            out[(ty * 4 + 2 * ip + 1) * KK + tx * 4 + j] = hi;
        }
}

// ---------------- kernel 3: reduce Gram partials, add identity ---------------
__global__ void k_greduce() {
    int i = blockIdx.x * 256 + threadIdx.x;   // grid = 16
    float s = 0.f;
#pragma unroll
    for (int p = 0; p < NCHUNKS; p++) s += g_Gpart[p * KK * KK + i];
    if ((i >> 6) == (i & 63)) s += 1.0f;
    g_G[i] = s;
}

// ---------------- kernel 4: elementwise pass + deterministic compaction ------
// One barrier total. Compaction order = fixed permutation (by tid, then by
// iteration) — deterministic across replays, which is all the GEMM needs.
__global__ void k_ew(const float* __restrict__ targets, const float* __restrict__ rho,
                     const float* __restrict__ qs, const float* __restrict__ means,
                     const float* __restrict__ psi) {
    __shared__ unsigned warptot[8];
    __shared__ float wred[5 * 8];
    int b = blockIdx.x, tid = threadIdx.x;
    int lane = tid & 31, w = tid >> 5;
    float rho_s = rho[0];
    float logrho = logf(rho_s);
    const float* tg = targets + b * NN;
    const float* qp = qs + b * NN;
    const float* mp = means + b * NN;

    float uni = 0.f, extra = 0.f, wd2 = 0.f, slogpsi = 0.f, nb = 0.f;
    unsigned mask = 0;   // bit it set => UNMASKED at n = it*256 + tid

#pragma unroll
    for (int it = 0; it < 16; it++) {
        int n = it * 256 + tid;
        float t = tg[n], qv = qp[n], mu = mp[n], ps = psi[n];
        bool masked = (t >= rho_s);
        float dpv = 0.0f;
        if (masked) {
            float lt = logf(t);
            dpv = (lt - mu) * rsqrtf(ps);
            wd2 += dpv * dpv;
            slogpsi += logf(ps);
            nb += 1.0f;
            extra += logf(qv) - lt;
        } else {
            uni += log1pf(-qv) - logrho;
            mask |= (1u << it);
        }
        g_dp[b * NN + n] = dpv;
    }

    // block-wide exclusive scan of per-thread unmasked counts (1 barrier)
    unsigned cnt = __popc(mask);
    unsigned x = cnt;
#pragma unroll
    for (int o = 1; o < 32; o <<= 1) {
        unsigned y = __shfl_up_sync(0xffffffffu, x, o);
        if (lane >= o) x += y;
    }
    unsigned excl = x - cnt;
    if (lane == 31) warptot[w] = x;

    // fold scalar partials into warp sums while we're pre-barrier
    float vals[5] = {uni, extra, wd2, slogpsi, nb};
#pragma unroll
    for (int q5 = 0; q5 < 5; q5++) {
        float v = vals[q5];
#pragma unroll
        for (int off2 = 16; off2 > 0; off2 >>= 1) v += __shfl_xor_sync(0xffffffffu, v, off2);
        if (lane == 0) wred[q5 * 8 + w] = v;
    }
    __syncthreads();

    unsigned off = excl;
    for (int ww = 0; ww < w; ww++) off += warptot[ww];
    unsigned mm = mask;
    int* idxp = g_idx + b * NN;
    while (mm) {
        int it = __ffs(mm) - 1;
        mm &= mm - 1;
        idxp[off++] = it * 256 + tid;
    }

    if (tid == 0) {
        unsigned tot = 0;
#pragma unroll
        for (int ww = 0; ww < 8; ww++) tot += warptot[ww];
        g_cnt[b] = (int)tot;
#pragma unroll
        for (int q5 = 0; q5 < 5; q5++) {
            float s = 0.f;
#pragma unroll
            for (int ww = 0; ww < 8; ww++) s += wred[q5 * 8 + ww];
            g_scal[b * 8 + q5] = s;
        }
    }
}

// ---------------- kernel 5: partial U = dp @ Ct (batched, Ct reused) ---------
__global__ void k_upart() {
    __shared__ float DPt[64 * CS_STRIDE];
    __shared__ float Cts[64 * CS_STRIDE];
    int tid = threadIdx.x;
    int ty = tid >> 4, tx = tid & 15;
    int r = tid >> 2, q = tid & 3;
    int btile = blockIdx.x * 64;   // gridDim.x = 4
    int nch = blockIdx.y;          // gridDim.y = 16
    unsigned long long acc2[2][4];
#pragma unroll
    for (int ip = 0; ip < 2; ip++)
#pragma unroll
        for (int j = 0; j < 4; j++) acc2[ip][j] = 0ull;

    for (int sub = 0; sub < 4; sub++) {
        int n0 = nch * 256 + sub * 64;
        const float4* cs = (const float4*)(g_Ct + (n0 + r) * KK + q * 16);
        const float4* ds = (const float4*)(g_dp + (btile + r) * NN + n0 + q * 16);
#pragma unroll
        for (int i = 0; i < 4; i++) {
            *(float4*)&Cts[r * CS_STRIDE + q * 16 + i * 4] = cs[i];
            float4 dv = ds[i];
            DPt[(q * 16 + i * 4 + 0) * CS_STRIDE + r] = dv.x;
            DPt[(q * 16 + i * 4 + 1) * CS_STRIDE + r] = dv.y;
            DPt[(q * 16 + i * 4 + 2) * CS_STRIDE + r] = dv.z;
            DPt[(q * 16 + i * 4 + 3) * CS_STRIDE + r] = dv.w;
        }
        __syncthreads();
#pragma unroll 16
        for (int s = 0; s < 64; s++) {
            const unsigned long long* ap =
                (const unsigned long long*)&DPt[s * CS_STRIDE + ty * 4];
            unsigned long long a01 = ap[0], a23 = ap[1];
            float4 b4 = *(const float4*)&Cts[s * CS_STRIDE + tx * 4];
            unsigned long long bd0 = pack2(b4.x, b4.x), bd1 = pack2(b4.y, b4.y);
            unsigned long long bd2 = pack2(b4.z, b4.z), bd3 = pack2(b4.w, b4.w);
            fma2(acc2[0][0], a01, bd0); fma2(acc2[0][1], a01, bd1);
            fma2(acc2[0][2], a01, bd2); fma2(acc2[0][3], a01, bd3);
            fma2(acc2[1][0], a23, bd0); fma2(acc2[1][1], a23, bd1);
            fma2(acc2[1][2], a23, bd2); fma2(acc2[1][3], a23, bd3);
        }
        __syncthreads();
    }
#pragma unroll
    for (int ip = 0; ip < 2; ip++)
#pragma unroll
        for (int j = 0; j < 4; j++) {
            float lo, hi;
            unpack2(acc2[ip][j], lo, hi);
            g_Upart[nch * BB * KK + (btile + ty * 4 + 2 * ip + 0) * KK + (tx * 4 + j)] = lo;
            g_Upart[nch * BB * KK + (btile + ty * 4 + 2 * ip + 1) * KK + (tx * 4 + j)] = hi;
        }
}

// ---------------- kernel 6: per-b correction SYRK + Cholesky + solve ---------
__global__ void __launch_bounds__(256, 2) k_main(float* __restrict__ out) {
    __shared__ float Cs[64 * CS_STRIDE];
    __shared__ float As[64 * AS_STRIDE];
    __shared__ float u_s[64], col_s[64], diag_s[64], z_s[64];
    int b = blockIdx.x, tid = threadIdx.x;
    int ty = tid >> 4, tx = tid & 15;
    int r = tid >> 2, q = tid & 3;

    if (tid < 64) {
        float s = 0.f;
#pragma unroll
        for (int p = 0; p < NCHUNKS; p++) s += g_Upart[p * BB * KK + b * KK + tid];
        u_s[tid] = s;
    }

    // accumulate POSITIVE correction S = sum_{unmasked} c' c'^T, subtract at end
    unsigned long long acc2[2][4];
#pragma unroll
    for (int ip = 0; ip < 2; ip++)
#pragma unroll
        for (int j = 0; j < 4; j++) acc2[ip][j] = 0ull;

    int cnt = g_cnt[b];
    int tiles = (cnt + 63) >> 6;
    const int* idxp = g_idx + b * NN;

    for (int t = 0; t < tiles; t++) {
        int p = t * 64 + r;
        if (p < cnt) {
            int n = idxp[p];
            const float4* src = (const float4*)(g_Ct + n * KK + q * 16);
#pragma unroll
            for (int i = 0; i < 4; i++)
                *(float4*)&Cs[r * CS_STRIDE + q * 16 + i * 4] = src[i];
        } else {
            float4 z4 = {0.f, 0.f, 0.f, 0.f};
#pragma unroll
            for (int i = 0; i < 4; i++)
                *(float4*)&Cs[r * CS_STRIDE + q * 16 + i * 4] = z4;
        }
        __syncthreads();
#pragma unroll 16
        for (int s = 0; s < 64; s++) {
            const unsigned long long* ap =
                (const unsigned long long*)&Cs[s * CS_STRIDE + ty * 4];
            unsigned long long a01 = ap[0], a23 = ap[1];
            float4 b4 = *(const float4*)&Cs[s * CS_STRIDE + tx * 4];
            unsigned long long bd0 = pack2(b4.x, b4.x), bd1 = pack2(b4.y, b4.y);
            unsigned long long bd2 = pack2(b4.z, b4.z), bd3 = pack2(b4.w, b4.w);
            fma2(acc2[0][0], a01, bd0); fma2(acc2[0][1], a01, bd1);
            fma2(acc2[0][2], a01, bd2); fma2(acc2[0][3], a01, bd3);
            fma2(acc2[1][0], a23, bd0); fma2(acc2[1][1], a23, bd1);
            fma2(acc2[1][2], a23, bd2); fma2(acc2[1][3], a23, bd3);
        }
        __syncthreads();
    }

    // As = G - S
#pragma unroll
    for (int ip = 0; ip < 2; ip++)
#pragma unroll
        for (int j = 0; j < 4; j++) {
            float lo, hi;
            unpack2(acc2[ip][j], lo, hi);
            int r0 = ty * 4 + 2 * ip, c0 = tx * 4 + j;
            As[(r0 + 0) * AS_STRIDE + c0] = g_G[(r0 + 0) * KK + c0] - lo;
            As[(r0 + 1) * AS_STRIDE + c0] = g_G[(r0 + 1) * KK + c0] - hi;
        }
    __syncthreads();

    // ---- Cholesky (lower), block-parallel, div-free update ----
    float logdet = 0.f;
    int urow = tid >> 6;       // 0..3
    int ucol = tid & 63;       // 0..63
    for (int j = 0; j < 64; j++) {
        float d = sqrtf(As[j * AS_STRIDE + j]);   // redundant per-thread (post-sync read)
        logdet += logf(d);
        float inv = 1.0f / d;
        if (tid == 0) diag_s[j] = d;
        int i2 = j + 1 + tid;
        if (i2 < 64) {
            float v = As[i2 * AS_STRIDE + j] * inv;
            As[i2 * AS_STRIDE + j] = v;
            col_s[i2] = v;
        }
        __syncthreads();
        int cc = j + 1 + ucol;
        if (cc < 64) {
            float cv = col_s[cc];
            for (int rr = j + 1 + urow; rr < 64; rr += 4)
                As[rr * AS_STRIDE + cc] -= col_s[rr] * cv;
        }
        __syncthreads();
    }

    // ---- forward solve L z = u;  u^T A^-1 u = ||z||^2 ----
    if (tid < 64) z_s[tid] = u_s[tid];
    __syncthreads();
    float zz = 0.f;
    for (int j = 0; j < 64; j++) {
        float zj = z_s[j] / diag_s[j];
        zz += zj * zj;
        int rr = j + 1 + tid;
        if (rr < 64) z_s[rr] -= As[rr * AS_STRIDE + j] * zj;
        __syncthreads();
    }

    if (tid == 0) {
        float uni   = g_scal[b * 8 + 0];
        float extra = g_scal[b * 8 + 1];
        float wd2   = g_scal[b * 8 + 2];
        float slp   = g_scal[b * 8 + 3];
        float nb    = g_scal[b * 8 + 4];
        float logdetA = 2.0f * logdet;
        const float LOG2PI = 1.8378770664093453f;
        float gauss = -0.5f * (nb * LOG2PI + (slp + logdetA) + (wd2 - zz));
        out[b] = uni + gauss + extra;
    }
}

// ---------------- launch ------------------------------------------------------
extern "C" void kernel_launch(void* const* d_in, const int* in_sizes, int n_in,
                              void* d_out, int out_size) {
    const float* targets = (const float*)d_in[0];
    const float* rho     = (const float*)d_in[1];
    const float* qs      = (const float*)d_in[2];
    const float* means   = (const float*)d_in[3];
    const float* C       = (const float*)d_in[4];
    const float* psi     = (const float*)d_in[5];
    float* out = (float*)d_out;

    k_prep<<<(NN * KK) / 256, 256>>>(C, psi);
    k_gpart<<<NCHUNKS, 256>>>();
    k_greduce<<<(KK * KK) / 256, 256>>>();
    k_ew<<<BB, 256>>>(targets, rho, qs, means, psi);
    k_upart<<<dim3(BB / 64, NCHUNKS), 256>>>();
    k_main<<<BB, 256>>>(out);
}

// round 8
// speedup vs baseline: 1.1871x; 1.0550x over previous
#include <cuda_runtime.h>
#include <math.h>

#define BB 256
#define NN 4096
#define KK 64
#define CS_STRIDE 68   // 64 + 4 pad; 68*4 = 272 bytes, keeps 16B alignment
#define AS_STRIDE 65
#define NCHUNKS 16     // N / 256

// ---------------- packed f32x2 helpers (Blackwell full-rate fp32) ------------
__device__ __forceinline__ void fma2(unsigned long long& acc, unsigned long long a,
                                     unsigned long long b) {
    asm("fma.rn.f32x2 %0, %1, %2, %0;" : "+l"(acc) : "l"(a), "l"(b));
}
__device__ __forceinline__ unsigned long long pack2(float lo, float hi) {
    unsigned long long r;
    asm("mov.b64 %0, {%1, %2};" : "=l"(r) : "f"(lo), "f"(hi));
    return r;
}
__device__ __forceinline__ void unpack2(unsigned long long v, float& lo, float& hi) {
    asm("mov.b64 {%0, %1}, %2;" : "=f"(lo), "=f"(hi) : "l"(v));
}

// ---------------- scratch (static device globals; no allocation) -------------
// g_Ct has one extra ZERO row at n = NN (never written; .bss zero-init) used to
// pad gather tiles so k_main's inner loop is branch-free.
__device__ float g_Ct[(NN + 1) * KK];        // C'[n][k] = C[k][n] * rsqrt(psi[n])
__device__ float g_rpsi[NN];                 // rsqrt(psi)
__device__ float g_lpsi[NN];                 // log(psi)
__device__ float g_Gpart[NCHUNKS * KK * KK]; // partial Gram matrices
__device__ float g_G[KK * KK];               // I + C' C'^T
__device__ float g_dp[BB * NN];              // masked residual / sqrt(psi)
__device__ int   g_idx[BB * NN];             // compacted unmasked indices (padded with NN)
__device__ int   g_cnt[BB];
__device__ float g_scal[BB * 8];             // per-row scalar reductions
__device__ float g_Upart[NCHUNKS * BB * KK]; // partial u vectors

// ---------------- kernel 1: scaled transposed C + psi precompute -------------
__global__ void k_prep(const float* __restrict__ C, const float* __restrict__ psi) {
    int idx = blockIdx.x * 256 + threadIdx.x;   // idx = k*NN + n
    int n = idx & (NN - 1);
    int k = idx >> 12;
    float ps = psi[n];
    float rp = rsqrtf(ps);
    g_Ct[n * KK + k] = C[idx] * rp;
    if (k == 0) {                // one thread per n
        g_rpsi[n] = rp;
        g_lpsi[n] = logf(ps);
    }
}

// ---------------- kernel 2: partial Gram (SYRK over 256-column chunks) -------
__global__ void k_gpart() {
    __shared__ float Cs[64 * CS_STRIDE];
    int tid = threadIdx.x;
    int ty = tid >> 4, tx = tid & 15;
    int r = tid >> 2, q = tid & 3;
    unsigned long long acc2[2][4];
#pragma unroll
    for (int ip = 0; ip < 2; ip++)
#pragma unroll
        for (int j = 0; j < 4; j++) acc2[ip][j] = 0ull;

    for (int sub = 0; sub < 4; sub++) {
        int n0 = blockIdx.x * 256 + sub * 64;
        const float4* src = (const float4*)(g_Ct + (n0 + r) * KK + q * 16);
#pragma unroll
        for (int i = 0; i < 4; i++)
            *(float4*)&Cs[r * CS_STRIDE + q * 16 + i * 4] = src[i];
        __syncthreads();
#pragma unroll 16
        for (int s = 0; s < 64; s++) {
            const unsigned long long* ap =
                (const unsigned long long*)&Cs[s * CS_STRIDE + ty * 4];
            unsigned long long a01 = ap[0], a23 = ap[1];
            float4 b4 = *(const float4*)&Cs[s * CS_STRIDE + tx * 4];
            unsigned long long bd0 = pack2(b4.x, b4.x), bd1 = pack2(b4.y, b4.y);
            unsigned long long bd2 = pack2(b4.z, b4.z), bd3 = pack2(b4.w, b4.w);
            fma2(acc2[0][0], a01, bd0); fma2(acc2[0][1], a01, bd1);
            fma2(acc2[0][2], a01, bd2); fma2(acc2[0][3], a01, bd3);
            fma2(acc2[1][0], a23, bd0); fma2(acc2[1][1], a23, bd1);
            fma2(acc2[1][2], a23, bd2); fma2(acc2[1][3], a23, bd3);
        }
        __syncthreads();
    }
    float* out = g_Gpart + blockIdx.x * KK * KK;
#pragma unroll
    for (int ip = 0; ip < 2; ip++)
#pragma unroll
        for (int j = 0; j < 4; j++) {
            float lo, hi;
            unpack2(acc2[ip][j], lo, hi);
            out[(ty * 4 + 2 * ip + 0) * KK + tx * 4 + j] = lo;
            out[(ty * 4 + 2 * ip + 1) * KK + tx * 4 + j] = hi;
        }
}

// ---------------- kernel 3: elementwise + compaction (block = 512) -----------
// One barrier. Blocks 0..15 additionally reduce g_Gpart -> g_G. Compaction
// order is a fixed deterministic permutation (by tid, then iteration).
__global__ void k_ew(const float* __restrict__ targets, const float* __restrict__ rho,
                     const float* __restrict__ qs, const float* __restrict__ means) {
    __shared__ unsigned warptot[16];
    __shared__ float wred[5 * 16];
    int b = blockIdx.x, tid = threadIdx.x;
    int lane = tid & 31, w = tid >> 5;
    float rho_s = rho[0];
    float logrho = logf(rho_s);
    const float* tg = targets + b * NN;
    const float* qp = qs + b * NN;
    const float* mp = means + b * NN;

    float uni = 0.f, extra = 0.f, wd2 = 0.f, slogpsi = 0.f, nb = 0.f;
    unsigned mask = 0;   // bit it set => UNMASKED at n = it*512 + tid

#pragma unroll
    for (int it = 0; it < 8; it++) {
        int n = it * 512 + tid;
        float t = tg[n], qv = qp[n], mu = mp[n];
        bool masked = (t >= rho_s);
        float dpv = 0.0f;
        if (masked) {
            float lt = logf(t);
            dpv = (lt - mu) * g_rpsi[n];
            wd2 += dpv * dpv;
            slogpsi += g_lpsi[n];
            nb += 1.0f;
            extra += logf(qv) - lt;
        } else {
            uni += log1pf(-qv) - logrho;
            mask |= (1u << it);
        }
        g_dp[b * NN + n] = dpv;
    }

    // block-wide exclusive scan of per-thread unmasked counts (1 barrier)
    unsigned cnt = __popc(mask);
    unsigned x = cnt;
#pragma unroll
    for (int o = 1; o < 32; o <<= 1) {
        unsigned y = __shfl_up_sync(0xffffffffu, x, o);
        if (lane >= o) x += y;
    }
    unsigned excl = x - cnt;
    if (lane == 31) warptot[w] = x;

    float vals[5] = {uni, extra, wd2, slogpsi, nb};
#pragma unroll
    for (int q5 = 0; q5 < 5; q5++) {
        float v = vals[q5];
#pragma unroll
        for (int off2 = 16; off2 > 0; off2 >>= 1) v += __shfl_xor_sync(0xffffffffu, v, off2);
        if (lane == 0) wred[q5 * 16 + w] = v;
    }
    __syncthreads();

    unsigned off = excl;
    for (int ww = 0; ww < w; ww++) off += warptot[ww];
    unsigned tot = 0;
#pragma unroll
    for (int ww = 0; ww < 16; ww++) tot += warptot[ww];

    unsigned mm = mask;
    int* idxp = g_idx + b * NN;
    while (mm) {
        int it = __ffs(mm) - 1;
        mm &= mm - 1;
        idxp[off++] = it * 512 + tid;
    }
    // pad to a multiple of 64 with the zero row index NN (branch-free k_main)
    unsigned pad = ((tot + 63u) & ~63u) - tot;
    if ((unsigned)tid < pad) idxp[tot + tid] = NN;

    if (tid == 0) {
        g_cnt[b] = (int)tot;
#pragma unroll
        for (int q5 = 0; q5 < 5; q5++) {
            float s = 0.f;
#pragma unroll
            for (int ww = 0; ww < 16; ww++) s += wred[q5 * 16 + ww];
            g_scal[b * 8 + q5] = s;
        }
    }

    // side job: blocks 0..15 reduce the Gram partials (256 elems each)
    if (b < 16 && tid < 256) {
        int gi = b * 256 + tid;
        float s = 0.f;
#pragma unroll
        for (int p = 0; p < NCHUNKS; p++) s += g_Gpart[p * KK * KK + gi];
        if ((gi >> 6) == (gi & 63)) s += 1.0f;
        g_G[gi] = s;
    }
}

// ---------------- kernel 4: partial U = dp @ Ct (batched, Ct reused) ---------
__global__ void k_upart() {
    __shared__ float DPt[64 * CS_STRIDE];
    __shared__ float Cts[64 * CS_STRIDE];
    int tid = threadIdx.x;
    int ty = tid >> 4, tx = tid & 15;
    int r = tid >> 2, q = tid & 3;
    int btile = blockIdx.x * 64;   // gridDim.x = 4
    int nch = blockIdx.y;          // gridDim.y = 16
    unsigned long long acc2[2][4];
#pragma unroll
    for (int ip = 0; ip < 2; ip++)
#pragma unroll
        for (int j = 0; j < 4; j++) acc2[ip][j] = 0ull;

    for (int sub = 0; sub < 4; sub++) {
        int n0 = nch * 256 + sub * 64;
        const float4* cs = (const float4*)(g_Ct + (n0 + r) * KK + q * 16);
        const float4* ds = (const float4*)(g_dp + (btile + r) * NN + n0 + q * 16);
#pragma unroll
        for (int i = 0; i < 4; i++) {
            *(float4*)&Cts[r * CS_STRIDE + q * 16 + i * 4] = cs[i];
            float4 dv = ds[i];
            DPt[(q * 16 + i * 4 + 0) * CS_STRIDE + r] = dv.x;
            DPt[(q * 16 + i * 4 + 1) * CS_STRIDE + r] = dv.y;
            DPt[(q * 16 + i * 4 + 2) * CS_STRIDE + r] = dv.z;
            DPt[(q * 16 + i * 4 + 3) * CS_STRIDE + r] = dv.w;
        }
        __syncthreads();
#pragma unroll 16
        for (int s = 0; s < 64; s++) {
            const unsigned long long* ap =
                (const unsigned long long*)&DPt[s * CS_STRIDE + ty * 4];
            unsigned long long a01 = ap[0], a23 = ap[1];
            float4 b4 = *(const float4*)&Cts[s * CS_STRIDE + tx * 4];
            unsigned long long bd0 = pack2(b4.x, b4.x), bd1 = pack2(b4.y, b4.y);
            unsigned long long bd2 = pack2(b4.z, b4.z), bd3 = pack2(b4.w, b4.w);
            fma2(acc2[0][0], a01, bd0); fma2(acc2[0][1], a01, bd1);
            fma2(acc2[0][2], a01, bd2); fma2(acc2[0][3], a01, bd3);
            fma2(acc2[1][0], a23, bd0); fma2(acc2[1][1], a23, bd1);
            fma2(acc2[1][2], a23, bd2); fma2(acc2[1][3], a23, bd3);
        }
        __syncthreads();
    }
#pragma unroll
    for (int ip = 0; ip < 2; ip++)
#pragma unroll
        for (int j = 0; j < 4; j++) {
            float lo, hi;
            unpack2(acc2[ip][j], lo, hi);
            g_Upart[nch * BB * KK + (btile + ty * 4 + 2 * ip + 0) * KK + (tx * 4 + j)] = lo;
            g_Upart[nch * BB * KK + (btile + ty * 4 + 2 * ip + 1) * KK + (tx * 4 + j)] = hi;
        }
}

// ---------------- kernel 5: per-b correction SYRK + Cholesky + solve ---------
// Single smem tile (48KB static limit) + REGISTER prefetch: tile t+1's gather
// LDGs are issued before computing tile t, hiding L2/DRAM latency.
__global__ void __launch_bounds__(256, 2) k_main(float* __restrict__ out) {
    __shared__ float Cs[64 * CS_STRIDE];
    __shared__ float As[64 * AS_STRIDE];
    __shared__ float u_s[64], col_s[64], diag_s[64], z_s[64], lred[2];
    int b = blockIdx.x, tid = threadIdx.x;
    int ty = tid >> 4, tx = tid & 15;
    int r = tid >> 2, q = tid & 3;

    if (tid < 64) {
        float s = 0.f;
#pragma unroll
        for (int p = 0; p < NCHUNKS; p++) s += g_Upart[p * BB * KK + b * KK + tid];
        u_s[tid] = s;
    }

    unsigned long long acc2[2][4];
#pragma unroll
    for (int ip = 0; ip < 2; ip++)
#pragma unroll
        for (int j = 0; j < 4; j++) acc2[ip][j] = 0ull;

    int cnt = g_cnt[b];
    int tiles = (cnt + 63) >> 6;
    const int* idxp = g_idx + b * NN;

    float4 pre[4];
    if (tiles > 0) {
        int n = idxp[r];
        const float4* src = (const float4*)(g_Ct + n * KK + q * 16);
#pragma unroll
        for (int i = 0; i < 4; i++) pre[i] = src[i];
    }
    for (int t = 0; t < tiles; t++) {
#pragma unroll
        for (int i = 0; i < 4; i++)
            *(float4*)&Cs[r * CS_STRIDE + q * 16 + i * 4] = pre[i];
        __syncthreads();
        // prefetch next tile into registers; LDGs overlap the compute below
        if (t + 1 < tiles) {
            int n = idxp[(t + 1) * 64 + r];
            const float4* src = (const float4*)(g_Ct + n * KK + q * 16);
#pragma unroll
            for (int i = 0; i < 4; i++) pre[i] = src[i];
        }
#pragma unroll 16
        for (int s = 0; s < 64; s++) {
            const unsigned long long* ap =
                (const unsigned long long*)&Cs[s * CS_STRIDE + ty * 4];
            unsigned long long a01 = ap[0], a23 = ap[1];
            float4 b4 = *(const float4*)&Cs[s * CS_STRIDE + tx * 4];
            unsigned long long bd0 = pack2(b4.x, b4.x), bd1 = pack2(b4.y, b4.y);
            unsigned long long bd2 = pack2(b4.z, b4.z), bd3 = pack2(b4.w, b4.w);
            fma2(acc2[0][0], a01, bd0); fma2(acc2[0][1], a01, bd1);
            fma2(acc2[0][2], a01, bd2); fma2(acc2[0][3], a01, bd3);
            fma2(acc2[1][0], a23, bd0); fma2(acc2[1][1], a23, bd1);
            fma2(acc2[1][2], a23, bd2); fma2(acc2[1][3], a23, bd3);
        }
        __syncthreads();
    }

    // As = G - S
#pragma unroll
    for (int ip = 0; ip < 2; ip++)
#pragma unroll
        for (int j = 0; j < 4; j++) {
            float lo, hi;
            unpack2(acc2[ip][j], lo, hi);
            int r0 = ty * 4 + 2 * ip, c0 = tx * 4 + j;
            As[(r0 + 0) * AS_STRIDE + c0] = g_G[(r0 + 0) * KK + c0] - lo;
            As[(r0 + 1) * AS_STRIDE + c0] = g_G[(r0 + 1) * KK + c0] - hi;
        }
    __syncthreads();

    // ---- Cholesky (lower), block-parallel, div-free update, no log in chain --
    int urow = tid >> 6;       // 0..3
    int ucol = tid & 63;       // 0..63
    for (int j = 0; j < 64; j++) {
        float d = sqrtf(As[j * AS_STRIDE + j]);
        float inv = 1.0f / d;
        if (tid == 0) diag_s[j] = d;
        int i2 = j + 1 + tid;
        if (i2 < 64) {
            float v = As[i2 * AS_STRIDE + j] * inv;
            As[i2 * AS_STRIDE + j] = v;
            col_s[i2] = v;
        }
        __syncthreads();
        int cc = j + 1 + ucol;
        if (cc < 64) {
            float cv = col_s[cc];
            for (int rr = j + 1 + urow; rr < 64; rr += 4)
                As[rr * AS_STRIDE + cc] -= col_s[rr] * cv;
        }
        __syncthreads();
    }

    // ---- forward solve L z = u;  u^T A^-1 u = ||z||^2 ----
    if (tid < 64) z_s[tid] = u_s[tid];
    __syncthreads();
    float zz = 0.f;
    for (int j = 0; j < 64; j++) {
        float zj = z_s[j] / diag_s[j];
        zz += zj * zj;
        int rr = j + 1 + tid;
        if (rr < 64) z_s[rr] -= As[rr * AS_STRIDE + j] * zj;
        __syncthreads();
    }

    // ---- parallel logdet from diag ----
    if (tid < 64) {
        float lg = logf(diag_s[tid]);
#pragma unroll
        for (int o = 16; o > 0; o >>= 1) lg += __shfl_xor_sync(0xffffffffu, lg, o);
        if ((tid & 31) == 0) lred[tid >> 5] = lg;
    }
    __syncthreads();

    if (tid == 0) {
        float uni   = g_scal[b * 8 + 0];
        float extra = g_scal[b * 8 + 1];
        float wd2   = g_scal[b * 8 + 2];
        float slp   = g_scal[b * 8 + 3];
        float nb    = g_scal[b * 8 + 4];
        float logdetA = 2.0f * (lred[0] + lred[1]);
        const float LOG2PI = 1.8378770664093453f;
        float gauss = -0.5f * (nb * LOG2PI + (slp + logdetA) + (wd2 - zz));
        out[b] = uni + gauss + extra;
    }
}

// ---------------- launch ------------------------------------------------------
extern "C" void kernel_launch(void* const* d_in, const int* in_sizes, int n_in,
                              void* d_out, int out_size) {
    const float* targets = (const float*)d_in[0];
    const float* rho     = (const float*)d_in[1];
    const float* qs      = (const float*)d_in[2];
    const float* means   = (const float*)d_in[3];
    const float* C       = (const float*)d_in[4];
    const float* psi     = (const float*)d_in[5];
    float* out = (float*)d_out;

    k_prep<<<(NN * KK) / 256, 256>>>(C, psi);
    k_gpart<<<NCHUNKS, 256>>>();
    k_ew<<<BB, 512>>>(targets, rho, qs, means);
    k_upart<<<dim3(BB / 64, NCHUNKS), 256>>>();
    k_main<<<BB, 256>>>(out);
}

// round 9
// speedup vs baseline: 1.2651x; 1.0658x over previous
#include <cuda_runtime.h>
#include <math.h>

#define BB 256
#define NN 4096
#define KK 64
#define CS_STRIDE 68   // 64 + 4 pad; 272 bytes, keeps 16B alignment
#define DP_STRIDE 34   // 32 + 2 pad; even => 8B-aligned LDS.64 rows
#define AS_STRIDE 65
#define NGPART 64      // Gram partial chunks (64 columns each)
#define NUPART 64      // U partial chunks (64 columns each)

// ---------------- packed f32x2 helpers (Blackwell full-rate fp32) ------------
__device__ __forceinline__ void fma2(unsigned long long& acc, unsigned long long a,
                                     unsigned long long b) {
    asm("fma.rn.f32x2 %0, %1, %2, %0;" : "+l"(acc) : "l"(a), "l"(b));
}
__device__ __forceinline__ unsigned long long pack2(float lo, float hi) {
    unsigned long long r;
    asm("mov.b64 %0, {%1, %2};" : "=l"(r) : "f"(lo), "f"(hi));
    return r;
}
__device__ __forceinline__ void unpack2(unsigned long long v, float& lo, float& hi) {
    asm("mov.b64 {%0, %1}, %2;" : "=f"(lo), "=f"(hi) : "l"(v));
}

// ---------------- scratch (static device globals; no allocation) -------------
// g_Ct has one extra ZERO row at n = NN (.bss zero-init) for branch-free
// padded gathers in k_main.
__device__ float g_Ct[(NN + 1) * KK];        // C'[n][k] = C[k][n] * rsqrt(psi[n])
__device__ float g_rpsi[NN];                 // rsqrt(psi)
__device__ float g_lpsi[NN];                 // log(psi)
__device__ float g_Gpart[NGPART * KK * KK];  // partial Gram matrices   (1 MB)
__device__ float g_G[KK * KK];               // I + C' C'^T
__device__ float g_dp[BB * NN];              // masked residual / sqrt(psi)
__device__ int   g_idx[BB * NN];             // compacted unmasked indices (padded)
__device__ int   g_cnt[BB];
__device__ float g_scal[BB * 8];             // per-row scalar reductions
__device__ float g_Upart[NUPART * BB * KK];  // partial u vectors        (4 MB)

// ---------------- kernel 1: scaled transposed C + psi precompute -------------
__global__ void k_prep(const float* __restrict__ C, const float* __restrict__ psi) {
    int idx = blockIdx.x * 256 + threadIdx.x;   // idx = k*NN + n
    int n = idx & (NN - 1);
    int k = idx >> 12;
    float ps = psi[n];
    float rp = rsqrtf(ps);
    g_Ct[n * KK + k] = C[idx] * rp;
    if (k == 0) {
        g_rpsi[n] = rp;
        g_lpsi[n] = logf(ps);
    }
}

// ---------------- kernel 2: partial Gram, one 64-column chunk per CTA --------
__global__ void k_gpart() {
    __shared__ float Cs[64 * CS_STRIDE];
    int tid = threadIdx.x;
    int ty = tid >> 4, tx = tid & 15;
    int r = tid >> 2, q = tid & 3;
    unsigned long long acc2[2][4];
#pragma unroll
    for (int ip = 0; ip < 2; ip++)
#pragma unroll
        for (int j = 0; j < 4; j++) acc2[ip][j] = 0ull;

    int n0 = blockIdx.x * 64;     // grid = 64
    const float4* src = (const float4*)(g_Ct + (n0 + r) * KK + q * 16);
#pragma unroll
    for (int i = 0; i < 4; i++)
        *(float4*)&Cs[r * CS_STRIDE + q * 16 + i * 4] = src[i];
    __syncthreads();
#pragma unroll 16
    for (int s = 0; s < 64; s++) {
        const unsigned long long* ap =
            (const unsigned long long*)&Cs[s * CS_STRIDE + ty * 4];
        unsigned long long a01 = ap[0], a23 = ap[1];
        float4 b4 = *(const float4*)&Cs[s * CS_STRIDE + tx * 4];
        unsigned long long bd0 = pack2(b4.x, b4.x), bd1 = pack2(b4.y, b4.y);
        unsigned long long bd2 = pack2(b4.z, b4.z), bd3 = pack2(b4.w, b4.w);
        fma2(acc2[0][0], a01, bd0); fma2(acc2[0][1], a01, bd1);
        fma2(acc2[0][2], a01, bd2); fma2(acc2[0][3], a01, bd3);
        fma2(acc2[1][0], a23, bd0); fma2(acc2[1][1], a23, bd1);
        fma2(acc2[1][2], a23, bd2); fma2(acc2[1][3], a23, bd3);
    }
    float* out = g_Gpart + blockIdx.x * KK * KK;
#pragma unroll
    for (int ip = 0; ip < 2; ip++)
#pragma unroll
        for (int j = 0; j < 4; j++) {
            float lo, hi;
            unpack2(acc2[ip][j], lo, hi);
            out[(ty * 4 + 2 * ip + 0) * KK + tx * 4 + j] = lo;
            out[(ty * 4 + 2 * ip + 1) * KK + tx * 4 + j] = hi;
        }
}

// ---------------- kernel 3: elementwise + compaction (block = 512) -----------
__global__ void k_ew(const float* __restrict__ targets, const float* __restrict__ rho,
                     const float* __restrict__ qs, const float* __restrict__ means) {
    __shared__ unsigned warptot[16];
    __shared__ float wred[5 * 16];
    int b = blockIdx.x, tid = threadIdx.x;
    int lane = tid & 31, w = tid >> 5;
    float rho_s = rho[0];
    float logrho = logf(rho_s);
    const float* tg = targets + b * NN;
    const float* qp = qs + b * NN;
    const float* mp = means + b * NN;

    float uni = 0.f, extra = 0.f, wd2 = 0.f, slogpsi = 0.f, nb = 0.f;
    unsigned mask = 0;   // bit it set => UNMASKED at n = it*512 + tid

#pragma unroll
    for (int it = 0; it < 8; it++) {
        int n = it * 512 + tid;
        float t = tg[n], qv = qp[n], mu = mp[n];
        bool masked = (t >= rho_s);
        float dpv = 0.0f;
        if (masked) {
            float lt = logf(t);
            dpv = (lt - mu) * g_rpsi[n];
            wd2 += dpv * dpv;
            slogpsi += g_lpsi[n];
            nb += 1.0f;
            extra += logf(qv) - lt;
        } else {
            uni += log1pf(-qv) - logrho;
            mask |= (1u << it);
        }
        g_dp[b * NN + n] = dpv;
    }

    unsigned cnt = __popc(mask);
    unsigned x = cnt;
#pragma unroll
    for (int o = 1; o < 32; o <<= 1) {
        unsigned y = __shfl_up_sync(0xffffffffu, x, o);
        if (lane >= o) x += y;
    }
    unsigned excl = x - cnt;
    if (lane == 31) warptot[w] = x;

    float vals[5] = {uni, extra, wd2, slogpsi, nb};
#pragma unroll
    for (int q5 = 0; q5 < 5; q5++) {
        float v = vals[q5];
#pragma unroll
        for (int off2 = 16; off2 > 0; off2 >>= 1) v += __shfl_xor_sync(0xffffffffu, v, off2);
        if (lane == 0) wred[q5 * 16 + w] = v;
    }
    __syncthreads();

    unsigned off = excl;
    for (int ww = 0; ww < w; ww++) off += warptot[ww];
    unsigned tot = 0;
#pragma unroll
    for (int ww = 0; ww < 16; ww++) tot += warptot[ww];

    unsigned mm = mask;
    int* idxp = g_idx + b * NN;
    while (mm) {
        int it = __ffs(mm) - 1;
        mm &= mm - 1;
        idxp[off++] = it * 512 + tid;
    }
    unsigned pad = ((tot + 63u) & ~63u) - tot;
    if ((unsigned)tid < pad) idxp[tot + tid] = NN;

    if (tid == 0) {
        g_cnt[b] = (int)tot;
#pragma unroll
        for (int q5 = 0; q5 < 5; q5++) {
            float s = 0.f;
#pragma unroll
            for (int ww = 0; ww < 16; ww++) s += wred[q5 * 16 + ww];
            g_scal[b * 8 + q5] = s;
        }
    }

    // side job: blocks 0..15 reduce the Gram partials (256 elems each)
    if (b < 16 && tid < 256) {
        int gi = b * 256 + tid;
        float s = 0.f;
#pragma unroll
        for (int p = 0; p < NGPART; p++) s += g_Gpart[p * KK * KK + gi];
        if ((gi >> 6) == (gi & 63)) s += 1.0f;
        g_G[gi] = s;
    }
}

// ---------------- kernel 4: partial U = dp @ Ct, grid (8 btiles, 64 chunks) --
__global__ void k_upart() {
    __shared__ float DPt[64 * DP_STRIDE];   // [n][b] transposed dp tile (32 rows)
    __shared__ float Cts[64 * CS_STRIDE];   // [n][k]
    int tid = threadIdx.x;
    int btile = blockIdx.x * 32;   // gridDim.x = 8
    int nch = blockIdx.y;          // gridDim.y = 64
    int n0 = nch * 64;

    // stage Ct tile: 64 n x 64 k
    {
        int r2 = tid >> 2, q2 = tid & 3;
        const float4* cs = (const float4*)(g_Ct + (n0 + r2) * KK + q2 * 16);
#pragma unroll
        for (int i = 0; i < 4; i++)
            *(float4*)&Cts[r2 * CS_STRIDE + q2 * 16 + i * 4] = cs[i];
    }
    // stage dp tile transposed: 32 rows x 64 n -> DPt[n][row]
    {
        int r = tid >> 3, q = tid & 7;      // r: 0..31 row, q: 8-float group
        const float4* ds = (const float4*)(g_dp + (btile + r) * NN + n0 + q * 8);
        float4 d0 = ds[0], d1 = ds[1];
        int nb0 = q * 8;
        DPt[(nb0 + 0) * DP_STRIDE + r] = d0.x;
        DPt[(nb0 + 1) * DP_STRIDE + r] = d0.y;
        DPt[(nb0 + 2) * DP_STRIDE + r] = d0.z;
        DPt[(nb0 + 3) * DP_STRIDE + r] = d0.w;
        DPt[(nb0 + 4) * DP_STRIDE + r] = d1.x;
        DPt[(nb0 + 5) * DP_STRIDE + r] = d1.y;
        DPt[(nb0 + 6) * DP_STRIDE + r] = d1.z;
        DPt[(nb0 + 7) * DP_STRIDE + r] = d1.w;
    }
    __syncthreads();

    // compute: 256 threads = 16 row-pairs x 16 col-quads
    int ty = tid >> 4, tx = tid & 15;       // rows (2ty,2ty+1), cols 4tx..4tx+3
    unsigned long long acc2[4] = {0ull, 0ull, 0ull, 0ull};
#pragma unroll 16
    for (int s = 0; s < 64; s++) {
        unsigned long long a01 =
            *(const unsigned long long*)&DPt[s * DP_STRIDE + 2 * ty];
        float4 b4 = *(const float4*)&Cts[s * CS_STRIDE + tx * 4];
        fma2(acc2[0], a01, pack2(b4.x, b4.x));
        fma2(acc2[1], a01, pack2(b4.y, b4.y));
        fma2(acc2[2], a01, pack2(b4.z, b4.z));
        fma2(acc2[3], a01, pack2(b4.w, b4.w));
    }
    float* outp = g_Upart + nch * BB * KK;
#pragma unroll
    for (int j = 0; j < 4; j++) {
        float lo, hi;
        unpack2(acc2[j], lo, hi);
        outp[(btile + 2 * ty + 0) * KK + tx * 4 + j] = lo;
        outp[(btile + 2 * ty + 1) * KK + tx * 4 + j] = hi;
    }
}

// ---------------- kernel 5: per-b correction SYRK + Cholesky + solve ---------
__global__ void __launch_bounds__(256, 2) k_main(float* __restrict__ out) {
    __shared__ float Cs[64 * CS_STRIDE];
    __shared__ float As[64 * AS_STRIDE];
    __shared__ float ured[4][64];
    __shared__ float u_s[64], col_s[64], diag_s[64], z_s[64], lred[2];
    int b = blockIdx.x, tid = threadIdx.x;
    int ty = tid >> 4, tx = tid & 15;
    int r = tid >> 2, q = tid & 3;

    // parallel u-reduce: 64 partials split 4 ways across 256 threads
    {
        int kk = tid & 63, gg = tid >> 6;
        float s = 0.f;
#pragma unroll
        for (int p = 0; p < 16; p++)
            s += g_Upart[(gg * 16 + p) * BB * KK + b * KK + kk];
        ured[gg][kk] = s;
    }

    unsigned long long acc2[2][4];
#pragma unroll
    for (int ip = 0; ip < 2; ip++)
#pragma unroll
        for (int j = 0; j < 4; j++) acc2[ip][j] = 0ull;

    int cnt = g_cnt[b];
    int tiles = (cnt + 63) >> 6;
    const int* idxp = g_idx + b * NN;

    float4 pre[4];
    if (tiles > 0) {
        int n = idxp[r];
        const float4* src = (const float4*)(g_Ct + n * KK + q * 16);
#pragma unroll
        for (int i = 0; i < 4; i++) pre[i] = src[i];
    }
    __syncthreads();                         // ured visible
    if (tid < 64)
        u_s[tid] = ured[0][tid] + ured[1][tid] + ured[2][tid] + ured[3][tid];

    for (int t = 0; t < tiles; t++) {
#pragma unroll
        for (int i = 0; i < 4; i++)
            *(float4*)&Cs[r * CS_STRIDE + q * 16 + i * 4] = pre[i];
        __syncthreads();
        if (t + 1 < tiles) {                 // register prefetch of next tile
            int n = idxp[(t + 1) * 64 + r];
            const float4* src = (const float4*)(g_Ct + n * KK + q * 16);
#pragma unroll
            for (int i = 0; i < 4; i++) pre[i] = src[i];
        }
#pragma unroll 16
        for (int s = 0; s < 64; s++) {
            const unsigned long long* ap =
                (const unsigned long long*)&Cs[s * CS_STRIDE + ty * 4];
            unsigned long long a01 = ap[0], a23 = ap[1];
            float4 b4 = *(const float4*)&Cs[s * CS_STRIDE + tx * 4];
            unsigned long long bd0 = pack2(b4.x, b4.x), bd1 = pack2(b4.y, b4.y);
            unsigned long long bd2 = pack2(b4.z, b4.z), bd3 = pack2(b4.w, b4.w);
            fma2(acc2[0][0], a01, bd0); fma2(acc2[0][1], a01, bd1);
            fma2(acc2[0][2], a01, bd2); fma2(acc2[0][3], a01, bd3);
            fma2(acc2[1][0], a23, bd0); fma2(acc2[1][1], a23, bd1);
            fma2(acc2[1][2], a23, bd2); fma2(acc2[1][3], a23, bd3);
        }
        __syncthreads();
    }

    // As = G - S
#pragma unroll
    for (int ip = 0; ip < 2; ip++)
#pragma unroll
        for (int j = 0; j < 4; j++) {
            float lo, hi;
            unpack2(acc2[ip][j], lo, hi);
            int r0 = ty * 4 + 2 * ip, c0 = tx * 4 + j;
            As[(r0 + 0) * AS_STRIDE + c0] = g_G[(r0 + 0) * KK + c0] - lo;
            As[(r0 + 1) * AS_STRIDE + c0] = g_G[(r0 + 1) * KK + c0] - hi;
        }
    __syncthreads();

    // ---- Cholesky (lower), block-parallel, div-free update ----
    int urow = tid >> 6;
    int ucol = tid & 63;
    for (int j = 0; j < 64; j++) {
        float d = sqrtf(As[j * AS_STRIDE + j]);
        float inv = 1.0f / d;
        if (tid == 0) diag_s[j] = d;
        int i2 = j + 1 + tid;
        if (i2 < 64) {
            float v = As[i2 * AS_STRIDE + j] * inv;
            As[i2 * AS_STRIDE + j] = v;
            col_s[i2] = v;
        }
        __syncthreads();
        int cc = j + 1 + ucol;
        if (cc < 64) {
            float cv = col_s[cc];
            for (int rr = j + 1 + urow; rr < 64; rr += 4)
                As[rr * AS_STRIDE + cc] -= col_s[rr] * cv;
        }
        __syncthreads();
    }

    // ---- forward solve L z = u;  u^T A^-1 u = ||z||^2 ----
    if (tid < 64) z_s[tid] = u_s[tid];
    __syncthreads();
    float zz = 0.f;
    for (int j = 0; j < 64; j++) {
        float zj = z_s[j] / diag_s[j];
        zz += zj * zj;
        int rr = j + 1 + tid;
        if (rr < 64) z_s[rr] -= As[rr * AS_STRIDE + j] * zj;
        __syncthreads();
    }

    // ---- parallel logdet from diag ----
    if (tid < 64) {
        float lg = logf(diag_s[tid]);
#pragma unroll
        for (int o = 16; o > 0; o >>= 1) lg += __shfl_xor_sync(0xffffffffu, lg, o);
        if ((tid & 31) == 0) lred[tid >> 5] = lg;
    }
    __syncthreads();

    if (tid == 0) {
        float uni   = g_scal[b * 8 + 0];
        float extra = g_scal[b * 8 + 1];
        float wd2   = g_scal[b * 8 + 2];
        float slp   = g_scal[b * 8 + 3];
        float nb    = g_scal[b * 8 + 4];
        float logdetA = 2.0f * (lred[0] + lred[1]);
        const float LOG2PI = 1.8378770664093453f;
        float gauss = -0.5f * (nb * LOG2PI + (slp + logdetA) + (wd2 - zz));
        out[b] = uni + gauss + extra;
    }
}

// ---------------- launch ------------------------------------------------------
extern "C" void kernel_launch(void* const* d_in, const int* in_sizes, int n_in,
                              void* d_out, int out_size) {
    const float* targets = (const float*)d_in[0];
    const float* rho     = (const float*)d_in[1];
    const float* qs      = (const float*)d_in[2];
    const float* means   = (const float*)d_in[3];
    const float* C       = (const float*)d_in[4];
    const float* psi     = (const float*)d_in[5];
    float* out = (float*)d_out;

    k_prep<<<(NN * KK) / 256, 256>>>(C, psi);
    k_gpart<<<NGPART, 256>>>();
    k_ew<<<BB, 512>>>(targets, rho, qs, means);
    k_upart<<<dim3(8, NUPART), 256>>>();
    k_main<<<BB, 256>>>(out);
}